// round 15
// baseline (speedup 1.0000x reference)
#include <cuda_runtime.h>
#include <cuda.h>
#include <cuda_fp16.h>
#include <math.h>
#include <cstdint>

// ---------------- problem constants ----------------
constexpr int B_ = 2;
constexpr int S_ = 2048;
constexpr int D_ = 2048;
constexpr int H_ = 16;
constexpr int Q_LORA = 1536;
constexpr int KV_LORA = 512;
constexpr int D_NOPE = 128;
constexpr int D_ROPE = 64;
constexpr int D_QK = D_NOPE + D_ROPE;   // 192
constexpr int D_V = 128;
constexpr int BS = B_ * S_;             // 4096
constexpr int BH = B_ * H_;             // 32
constexpr int NPROJ1 = Q_LORA + KV_LORA + D_ROPE;   // 2112

// ---------------- scratch (device globals) ----------------
__device__ __half g_proj1[(size_t)BS * NPROJ1];            // [q_a | kv_c_raw | k_pe_raw] (half)
__device__ __half g_xh   [(size_t)BS * D_];
__device__ __half g_wcomb[(size_t)NPROJ1 * D_];            // [Wqa ; Wkva]
__device__ __half g_wqbh [(size_t)H_ * D_QK * Q_LORA];
__device__ __half g_wkvbh[(size_t)H_ * (D_NOPE + D_V) * KV_LORA];
__device__ __half g_woh  [(size_t)D_ * H_ * D_V];
__device__ __half g_qan  [(size_t)BS * Q_LORA];
__device__ __half g_kvc  [(size_t)BS * KV_LORA];
__device__ __half g_qfull[(size_t)BS * (H_ * D_QK)];       // RoPE applied in epilogue
__device__ __half g_kvb  [(size_t)BS * (H_ * (D_NOPE + D_V))];
__device__ __half g_kpe  [(size_t)BS * D_ROPE];            // roped k_pe (shared across heads)
__device__ __half g_attn [(size_t)BS * (H_ * D_V)];

// ---------------- PTX helpers ----------------
__device__ __forceinline__ void mma_f16(float* c, const uint32_t* a, uint32_t b0, uint32_t b1) {
    asm volatile(
        "mma.sync.aligned.m16n8k16.row.col.f32.f16.f16.f32 "
        "{%0,%1,%2,%3}, {%4,%5,%6,%7}, {%8,%9}, {%0,%1,%2,%3};"
        : "+f"(c[0]), "+f"(c[1]), "+f"(c[2]), "+f"(c[3])
        : "r"(a[0]), "r"(a[1]), "r"(a[2]), "r"(a[3]), "r"(b0), "r"(b1));
}
__device__ __forceinline__ void ldsm4(uint32_t* r, uint32_t addr) {
    asm volatile("ldmatrix.sync.aligned.m8n8.x4.shared.b16 {%0,%1,%2,%3}, [%4];"
                 : "=r"(r[0]), "=r"(r[1]), "=r"(r[2]), "=r"(r[3]) : "r"(addr));
}
__device__ __forceinline__ void ldsm4t(uint32_t* r, uint32_t addr) {
    asm volatile("ldmatrix.sync.aligned.m8n8.x4.trans.shared.b16 {%0,%1,%2,%3}, [%4];"
                 : "=r"(r[0]), "=r"(r[1]), "=r"(r[2]), "=r"(r[3]) : "r"(addr));
}
__device__ __forceinline__ void cp16(uint32_t dst, const void* src, int bytes) {
    asm volatile("cp.async.cg.shared.global [%0], [%1], 16, %2;"
                 :: "r"(dst), "l"(src), "r"(bytes));
}
#define CP_COMMIT() asm volatile("cp.async.commit_group;" ::: "memory")
#define CP_WAIT(n)  asm volatile("cp.async.wait_group %0;" :: "n"(n) : "memory")

__device__ __forceinline__ uint32_t h2u(float a, float b) {
    __half2 h = __floats2half2_rn(a, b);
    return *(uint32_t*)&h;
}

// ---------------- fp16 mma.sync GEMM, cp.async 3-stage ----------------
// C[M,N] = alpha * A[M,K] * B[N,K]^T.
// flags bit2 (HOUT): C is __half.
// flags bit3 (ROPEQ): rotate per-head pe cols (d = gn % 192 >= 128) by freqs[row].
// flags bit4 (ROPEK): for gn >= 2048, also write rotated pair into kpe[row*64 + (gn-2048)].
#define STAGES   3
#define TILE_B   16384
#define STAGE_B  (2 * TILE_B)
#define SMEM_BYTES (STAGES * STAGE_B)     // 98304

__global__ void __launch_bounds__(256, 2) gemm_h(
    const __half* __restrict__ A, const __half* __restrict__ Bm, void* __restrict__ Cv,
    int M, int N, int K, int lda, int ldb, int ldc,
    float alpha, int flags,
    const float* __restrict__ freqs, __half* __restrict__ kpe)
{
    extern __shared__ __align__(16) char smc[];
    int t = threadIdx.x;
    int wid = t >> 5, lane = t & 31;
    int wm = wid & 3;
    int wn = wid >> 2;
    int lr = lane >> 2, lc = lane & 3;

    int m0 = blockIdx.y * 128;
    int n0 = blockIdx.x * 128;
    int NK = K >> 6;

    const __half* Abase = A + (long long)m0 * lda;
    const __half* Bbase = Bm + (long long)n0 * ldb;
    int nvB = N - n0; if (nvB > 128) nvB = 128;

    uint32_t sb = (uint32_t)__cvta_generic_to_shared(smc);

    int crow[4], ckc[4];
    uint32_t cdst[4];
#pragma unroll
    for (int i = 0; i < 4; i++) {
        int idx = t + i * 256;
        crow[i] = idx >> 3;
        ckc[i]  = idx & 7;
        cdst[i] = (uint32_t)(crow[i] * 128 + ((ckc[i] ^ (crow[i] & 7)) << 4));
    }

    auto issue = [&](int stage, int k0) {
        uint32_t dA = sb + (uint32_t)(stage * STAGE_B);
        uint32_t dB = dA + TILE_B;
#pragma unroll
        for (int i = 0; i < 4; i++) {
            int row = crow[i];
            cp16(dA + cdst[i], Abase + (long long)row * lda + k0 + ckc[i] * 8, 16);
            int brow = (row < nvB) ? row : 0;
            cp16(dB + cdst[i], Bbase + (long long)brow * ldb + k0 + ckc[i] * 8,
                 (row < nvB) ? 16 : 0);
        }
    };

    int aRow0 = wm * 32 + (lane & 15);
    int aSel  = (lane >> 4) & 1;
    int bRow0 = wn * 64 + (lane & 7) + (((lane >> 4) & 1) << 3);
    int bSel  = (lane >> 3) & 1;

    float acc[2][8][4];
#pragma unroll
    for (int i = 0; i < 2; i++)
#pragma unroll
        for (int j = 0; j < 8; j++)
#pragma unroll
            for (int k = 0; k < 4; k++) acc[i][j][k] = 0.f;

    issue(0, 0); CP_COMMIT();
    if (NK > 1) issue(1, 64);
    CP_COMMIT();
    int fetch = 2;

    for (int kt = 0; kt < NK; kt++) {
        CP_WAIT(1);
        __syncthreads();
        if (fetch < NK) issue(fetch % STAGES, fetch << 6);
        CP_COMMIT();
        fetch++;

        uint32_t sA = sb + (uint32_t)((kt % STAGES) * STAGE_B);
        uint32_t sB = sA + TILE_B;
#pragma unroll
        for (int ks = 0; ks < 4; ks++) {
            uint32_t a[2][4];
#pragma unroll
            for (int mf = 0; mf < 2; mf++) {
                int row = aRow0 + mf * 16;
                uint32_t addr = sA + row * 128 + ((((ks << 1) | aSel) ^ (row & 7)) << 4);
                ldsm4(a[mf], addr);
            }
#pragma unroll
            for (int nf2 = 0; nf2 < 4; nf2++) {
                int row = bRow0 + nf2 * 16;
                uint32_t addr = sB + row * 128 + ((((ks << 1) | bSel) ^ (row & 7)) << 4);
                uint32_t b[4];
                ldsm4(b, addr);
                mma_f16(acc[0][2 * nf2],     a[0], b[0], b[1]);
                mma_f16(acc[1][2 * nf2],     a[1], b[0], b[1]);
                mma_f16(acc[0][2 * nf2 + 1], a[0], b[2], b[3]);
                mma_f16(acc[1][2 * nf2 + 1], a[1], b[2], b[3]);
            }
        }
    }

    bool hout  = (flags & 4)  != 0;
    bool ropeq = (flags & 8)  != 0;
    bool ropek = (flags & 16) != 0;
#pragma unroll
    for (int mf = 0; mf < 2; mf++) {
        int r0 = m0 + wm * 32 + mf * 16 + lr;
#pragma unroll
        for (int nf = 0; nf < 8; nf++) {
            int gn = n0 + wn * 64 + nf * 8 + 2 * lc;
            if (gn < N) {
                float v0 = alpha * acc[mf][nf][0], v1 = alpha * acc[mf][nf][1];
                float v2 = alpha * acc[mf][nf][2], v3 = alpha * acc[mf][nf][3];
                if (ropeq) {
                    int d = gn % D_QK;
                    if (d >= D_NOPE) {
                        int p2 = d - D_NOPE;   // even pair offset into freqs row
                        {
                            const float* fr = freqs + (long long)(r0 & (S_ - 1)) * D_ROPE + p2;
                            float c = fr[0], sn = fr[1];
                            float t0 = v0 * c - v1 * sn, t1 = v0 * sn + v1 * c;
                            v0 = t0; v1 = t1;
                        }
                        {
                            const float* fr = freqs + (long long)((r0 + 8) & (S_ - 1)) * D_ROPE + p2;
                            float c = fr[0], sn = fr[1];
                            float t2 = v2 * c - v3 * sn, t3 = v2 * sn + v3 * c;
                            v2 = t2; v3 = t3;
                        }
                    }
                }
                if (ropek && gn >= (Q_LORA + KV_LORA)) {
                    int p2 = gn - (Q_LORA + KV_LORA);
                    {
                        const float* fr = freqs + (long long)(r0 & (S_ - 1)) * D_ROPE + p2;
                        float c = fr[0], sn = fr[1];
                        *(__half2*)(kpe + (long long)r0 * D_ROPE + p2) =
                            __floats2half2_rn(v0 * c - v1 * sn, v0 * sn + v1 * c);
                    }
                    {
                        const float* fr = freqs + (long long)((r0 + 8) & (S_ - 1)) * D_ROPE + p2;
                        float c = fr[0], sn = fr[1];
                        *(__half2*)(kpe + (long long)(r0 + 8) * D_ROPE + p2) =
                            __floats2half2_rn(v2 * c - v3 * sn, v2 * sn + v3 * c);
                    }
                }
                if (hout) {
                    __half* C = (__half*)Cv;
                    *(__half2*)(C + (long long)r0 * ldc + gn) = __floats2half2_rn(v0, v1);
                    *(__half2*)(C + (long long)(r0 + 8) * ldc + gn) = __floats2half2_rn(v2, v3);
                } else {
                    float* C = (float*)Cv;
                    *(float2*)(C + (long long)r0 * ldc + gn) = make_float2(v0, v1);
                    *(float2*)(C + (long long)(r0 + 8) * ldc + gn) = make_float2(v2, v3);
                }
            }
        }
    }
}

// ---------------- fused flash attention (validated R11-R14, unchanged) ----------------
#define FQ_B  49152
#define FK_B  49152
#define FV_B  32768
#define FSMEM (FQ_B + 2 * FK_B + 2 * FV_B)    // 212992

__global__ void __launch_bounds__(256, 1) flash_kernel(
    const __half* __restrict__ qfull, const __half* __restrict__ kvb,
    const __half* __restrict__ kpe, __half* __restrict__ attn, float scale)
{
    extern __shared__ __align__(16) char sm[];
    int t = threadIdx.x, wid = t >> 5, lane = t & 31;
    int qt = (int)gridDim.x - 1 - (int)blockIdx.x;     // longest tiles first
    int bh = blockIdx.y;
    int b = bh >> 4, h = bh & 15;
    int q0 = qt * 128;
    int wrow = wid * 16;
    int lr = lane >> 2, lc = lane & 3;

    const __half* Qg = qfull + ((long long)(b * S_ + q0) * H_ + h) * D_QK;
    const __half* Kn = kvb + ((long long)(b * S_) * H_ + h) * 256;
    const __half* Pe = kpe + (long long)b * S_ * D_ROPE;

    uint32_t sb = (uint32_t)__cvta_generic_to_shared(sm);
    uint32_t sQ  = sb;
    uint32_t sK0 = sb + FQ_B;
    uint32_t sV0 = sb + FQ_B + 2 * FK_B;

#pragma unroll
    for (int i = 0; i < 12; i++) {
        int c = i * 256 + t;
        int row = c / 24, ch = c % 24;
        uint32_t sw = (uint32_t)((ch & ~7) | ((ch & 7) ^ (row & 7)));
        cp16(sQ + row * 384 + sw * 16, Qg + (long long)row * (H_ * D_QK) + ch * 8, 16);
    }
    CP_COMMIT();

    auto issueKV = [&](int kt2, int buf2) {
        uint32_t dK = sK0 + (uint32_t)buf2 * FK_B;
        uint32_t dV = sV0 + (uint32_t)buf2 * FV_B;
        const __half* Ks = Kn + (long long)(kt2 * 128) * (H_ * 256);
        const __half* Ps = Pe + (long long)(kt2 * 128) * D_ROPE;
#pragma unroll
        for (int i = 0; i < 12; i++) {
            int c = i * 256 + t;
            int row = c / 24, ch = c % 24;
            uint32_t sw = (uint32_t)((ch & ~7) | ((ch & 7) ^ (row & 7)));
            const __half* src = (ch < 16)
                ? (Ks + (long long)row * (H_ * 256) + ch * 8)
                : (Ps + row * D_ROPE + (ch - 16) * 8);
            cp16(dK + row * 384 + sw * 16, src, 16);
        }
#pragma unroll
        for (int i = 0; i < 8; i++) {
            int c = i * 256 + t;
            int row = c >> 4, ch = c & 15;
            uint32_t sw = (uint32_t)((ch & ~7) | ((ch & 7) ^ (row & 7)));
            cp16(dV + row * 256 + sw * 16,
                 Ks + (long long)row * (H_ * 256) + 128 + ch * 8, 16);
        }
    };

    issueKV(0, 0); CP_COMMIT();

    float o[16][4];
#pragma unroll
    for (int i = 0; i < 16; i++)
#pragma unroll
        for (int j = 0; j < 4; j++) o[i][j] = 0.f;
    float m0 = -1e30f, m1 = -1e30f, l0 = 0.f, l1 = 0.f;

    int aSel = (lane >> 4) & 1;
    int bSub = (lane & 7) + (((lane >> 4) & 1) << 3);
    int bSel = (lane >> 3) & 1;
    int vs_lane = lane & 15;
    int vd_half = (lane >> 4) & 1;

    for (int kt = 0; kt <= qt; kt++) {
        int buf = kt & 1;
        if (kt < qt) { issueKV(kt + 1, buf ^ 1); CP_COMMIT(); CP_WAIT(1); }
        else         { CP_WAIT(0); }
        __syncthreads();

        uint32_t sK = sK0 + (uint32_t)buf * FK_B;
        uint32_t sV = sV0 + (uint32_t)buf * FV_B;

        float s[16][4];
#pragma unroll
        for (int i = 0; i < 16; i++)
#pragma unroll
            for (int j = 0; j < 4; j++) s[i][j] = 0.f;
#pragma unroll
        for (int ks = 0; ks < 12; ks++) {
            uint32_t a[4];
            {
                int r = wrow + (lane & 15);
                int ch = 2 * ks + aSel;
                uint32_t sw = (uint32_t)((ch & ~7) | ((ch & 7) ^ (r & 7)));
                ldsm4(a, sQ + r * 384 + sw * 16);
            }
#pragma unroll
            for (int nf2 = 0; nf2 < 8; nf2++) {
                int r = nf2 * 16 + bSub;
                int ch = 2 * ks + bSel;
                uint32_t sw = (uint32_t)((ch & ~7) | ((ch & 7) ^ (r & 7)));
                uint32_t bf[4];
                ldsm4(bf, sK + r * 384 + sw * 16);
                mma_f16(s[2 * nf2],     a, bf[0], bf[1]);
                mma_f16(s[2 * nf2 + 1], a, bf[2], bf[3]);
            }
        }

#pragma unroll
        for (int nf = 0; nf < 16; nf++)
#pragma unroll
            for (int j = 0; j < 4; j++) s[nf][j] *= scale;
        if (kt == qt) {
            int row0 = q0 + wrow + lr;
            int colb = q0 + 2 * lc;
#pragma unroll
            for (int nf = 0; nf < 16; nf++) {
                int c0 = colb + nf * 8;
                if (c0 > row0)         s[nf][0] = -1e30f;
                if (c0 + 1 > row0)     s[nf][1] = -1e30f;
                if (c0 > row0 + 8)     s[nf][2] = -1e30f;
                if (c0 + 1 > row0 + 8) s[nf][3] = -1e30f;
            }
        }

        float mx0 = -1e30f, mx1 = -1e30f;
#pragma unroll
        for (int nf = 0; nf < 16; nf++) {
            mx0 = fmaxf(mx0, fmaxf(s[nf][0], s[nf][1]));
            mx1 = fmaxf(mx1, fmaxf(s[nf][2], s[nf][3]));
        }
        mx0 = fmaxf(mx0, __shfl_xor_sync(0xffffffffu, mx0, 1));
        mx0 = fmaxf(mx0, __shfl_xor_sync(0xffffffffu, mx0, 2));
        mx1 = fmaxf(mx1, __shfl_xor_sync(0xffffffffu, mx1, 1));
        mx1 = fmaxf(mx1, __shfl_xor_sync(0xffffffffu, mx1, 2));
        float mn0 = fmaxf(m0, mx0), mn1 = fmaxf(m1, mx1);
        float al0 = __expf(m0 - mn0), al1 = __expf(m1 - mn1);
        m0 = mn0; m1 = mn1;
        float sum0 = 0.f, sum1 = 0.f;
#pragma unroll
        for (int nf = 0; nf < 16; nf++) {
            float p0 = __expf(s[nf][0] - mn0);
            float p1 = __expf(s[nf][1] - mn0);
            float p2 = __expf(s[nf][2] - mn1);
            float p3 = __expf(s[nf][3] - mn1);
            s[nf][0] = p0; s[nf][1] = p1; s[nf][2] = p2; s[nf][3] = p3;
            sum0 += p0 + p1; sum1 += p2 + p3;
        }
        sum0 += __shfl_xor_sync(0xffffffffu, sum0, 1);
        sum0 += __shfl_xor_sync(0xffffffffu, sum0, 2);
        sum1 += __shfl_xor_sync(0xffffffffu, sum1, 1);
        sum1 += __shfl_xor_sync(0xffffffffu, sum1, 2);
        l0 = l0 * al0 + sum0;
        l1 = l1 * al1 + sum1;
#pragma unroll
        for (int nf = 0; nf < 16; nf++) {
            o[nf][0] *= al0; o[nf][1] *= al0;
            o[nf][2] *= al1; o[nf][3] *= al1;
        }

#pragma unroll
        for (int j = 0; j < 8; j++) {
            uint32_t pa[4];
            pa[0] = h2u(s[2 * j][0],     s[2 * j][1]);
            pa[1] = h2u(s[2 * j][2],     s[2 * j][3]);
            pa[2] = h2u(s[2 * j + 1][0], s[2 * j + 1][1]);
            pa[3] = h2u(s[2 * j + 1][2], s[2 * j + 1][3]);
            int s_off = 16 * j + vs_lane;
#pragma unroll
            for (int nd2 = 0; nd2 < 8; nd2++) {
                int d_chunk = nd2 * 2 + vd_half;
                uint32_t sw = (uint32_t)((d_chunk & ~7) | ((d_chunk & 7) ^ (s_off & 7)));
                uint32_t bf[4];
                ldsm4t(bf, sV + s_off * 256 + sw * 16);
                mma_f16(o[2 * nd2],     pa, bf[0], bf[1]);
                mma_f16(o[2 * nd2 + 1], pa, bf[2], bf[3]);
            }
        }
        __syncthreads();
    }

    float il0 = 1.f / l0, il1 = 1.f / l1;
    int sg = q0 + wrow + lr;
    __half* a0 = attn + ((long long)(b * S_ + sg) * (H_ * D_V)) + h * D_V;
    __half* a1 = a0 + (long long)8 * (H_ * D_V);
#pragma unroll
    for (int nf = 0; nf < 16; nf++) {
        int d = nf * 8 + 2 * lc;
        *(__half2*)(a0 + d) = __floats2half2_rn(o[nf][0] * il0, o[nf][1] * il0);
        *(__half2*)(a1 + d) = __floats2half2_rn(o[nf][2] * il1, o[nf][3] * il1);
    }
}

// ---------------- fp32 -> fp16 convert ----------------
__global__ void cvt_f2h_kernel(const float* __restrict__ in, __half* __restrict__ out, int n4)
{
    int i = blockIdx.x * blockDim.x + threadIdx.x;
    int stride = gridDim.x * blockDim.x;
    for (; i < n4; i += stride) {
        float4 v = ((const float4*)in)[i];
        __half2 h0 = __floats2half2_rn(v.x, v.y);
        __half2 h1 = __floats2half2_rn(v.z, v.w);
        *(uint2*)(out + (size_t)i * 4) = make_uint2(*(uint32_t*)&h0, *(uint32_t*)&h1);
    }
}

// ---------------- fused dual RMSNorm (half in strided, half out) ----------------
__global__ void rmsnorm2_kernel(const __half* __restrict__ proj1,
                                const float* __restrict__ qw, const float* __restrict__ kw,
                                __half* __restrict__ qan, __half* __restrict__ kvc)
{
    long long row = blockIdx.x;
    int which = blockIdx.y;
    int width = which ? KV_LORA : Q_LORA;
    const __half* x = proj1 + row * NPROJ1 + (which ? Q_LORA : 0);
    const float* w = which ? kw : qw;
    __half* o = which ? (kvc + row * KV_LORA) : (qan + row * Q_LORA);
    __shared__ float red[256];
    int t = threadIdx.x;
    float ss = 0.f;
    for (int i = t; i < width; i += 256) { float v = __half2float(x[i]); ss += v * v; }
    red[t] = ss;
    __syncthreads();
    for (int s = 128; s > 0; s >>= 1) {
        if (t < s) red[t] += red[t + s];
        __syncthreads();
    }
    float scale = rsqrtf(red[0] / (float)width + 1e-6f);
    for (int i = t; i < width; i += 256)
        o[i] = __float2half_rn(__half2float(x[i]) * scale * w[i]);
}

// ---------------- launch helpers ----------------
static void launch_gemm_s(cudaStream_t st, const __half* A, const __half* Bm, void* C,
                          int M, int N, int K, int lda, int ldb, int ldc,
                          float alpha, int flags,
                          const float* freqs = nullptr, __half* kpe = nullptr)
{
    dim3 grid((N + 127) / 128, (M + 127) / 128, 1);
    gemm_h<<<grid, 256, SMEM_BYTES, st>>>(A, Bm, C, M, N, K, lda, ldb, ldc,
                                          alpha, flags, freqs, kpe);
}

static void launch_cvt_s(cudaStream_t st, const float* in, __half* out, size_t n)
{
    int n4 = (int)(n / 4);
    int blocks = (n4 + 255) / 256;
    if (blocks > 8192) blocks = 8192;
    cvt_f2h_kernel<<<blocks, 256, 0, st>>>(in, out, n4);
}

// ---- lazily-initialized streams/events (created ONCE on first call = part of
// the harness's pre-capture baseline; no per-call allocation) ----
struct StreamCtx {
    cudaStream_t s2, s3;
    cudaEvent_t eFork, eWc, eW, eW2, eWo, eN, e4;
    StreamCtx() {
        cudaStreamCreateWithFlags(&s2, cudaStreamNonBlocking);
        cudaStreamCreateWithFlags(&s3, cudaStreamNonBlocking);
        cudaEventCreateWithFlags(&eFork, cudaEventDisableTiming);
        cudaEventCreateWithFlags(&eWc,   cudaEventDisableTiming);
        cudaEventCreateWithFlags(&eW,    cudaEventDisableTiming);
        cudaEventCreateWithFlags(&eW2,   cudaEventDisableTiming);
        cudaEventCreateWithFlags(&eWo,   cudaEventDisableTiming);
        cudaEventCreateWithFlags(&eN,    cudaEventDisableTiming);
        cudaEventCreateWithFlags(&e4,    cudaEventDisableTiming);
    }
};

extern "C" void kernel_launch(void* const* d_in, const int* in_sizes, int n_in,
                              void* d_out, int out_size)
{
    const float* x     = (const float*)d_in[0];
    const float* freqs = (const float*)d_in[1];
    const float* Wqa   = (const float*)d_in[2];
    const float* qlnw  = (const float*)d_in[3];
    const float* Wqb   = (const float*)d_in[4];
    const float* Wkva  = (const float*)d_in[5];
    const float* kvlnw = (const float*)d_in[6];
    const float* Wkvb  = (const float*)d_in[7];
    const float* Wo    = (const float*)d_in[8];
    float* out = (float*)d_out;

    cudaFuncSetAttribute(gemm_h, cudaFuncAttributeMaxDynamicSharedMemorySize, SMEM_BYTES);
    cudaFuncSetAttribute(flash_kernel, cudaFuncAttributeMaxDynamicSharedMemorySize, FSMEM);

    __half *proj1, *xh, *wcomb, *wqbh, *wkvbh, *woh;
    __half *qan, *kvc, *qfull, *kvb, *kpe, *attn;
    cudaGetSymbolAddress((void**)&proj1,  g_proj1);
    cudaGetSymbolAddress((void**)&xh,     g_xh);
    cudaGetSymbolAddress((void**)&wcomb,  g_wcomb);
    cudaGetSymbolAddress((void**)&wqbh,   g_wqbh);
    cudaGetSymbolAddress((void**)&wkvbh,  g_wkvbh);
    cudaGetSymbolAddress((void**)&woh,    g_woh);
    cudaGetSymbolAddress((void**)&qan,    g_qan);
    cudaGetSymbolAddress((void**)&kvc,    g_kvc);
    cudaGetSymbolAddress((void**)&qfull,  g_qfull);
    cudaGetSymbolAddress((void**)&kvb,    g_kvb);
    cudaGetSymbolAddress((void**)&kpe,    g_kpe);
    cudaGetSymbolAddress((void**)&attn,   g_attn);

    const float SCALE = 1.0f / sqrtf((float)D_QK);
    const int HOUT = 4, ROPEQ = 8, ROPEK = 16;
    cudaStream_t s0 = 0;

    static StreamCtx ctx;          // created once on first (correctness) call
    cudaStream_t s2 = ctx.s2, s3 = ctx.s3;

    // fork s2/s3 off the capture (NULL) stream
    cudaEventRecord(ctx.eFork, s0);
    cudaStreamWaitEvent(s2, ctx.eFork, 0);
    cudaStreamWaitEvent(s3, ctx.eFork, 0);

    // s3: weight converts for later GEMMs
    launch_cvt_s(s3, Wqb,  wqbh,  (size_t)H_ * D_QK * Q_LORA);
    cudaEventRecord(ctx.eW, s3);
    launch_cvt_s(s3, Wkvb, wkvbh, (size_t)H_ * (D_NOPE + D_V) * KV_LORA);
    cudaEventRecord(ctx.eW2, s3);
    launch_cvt_s(s3, Wo,   woh,   (size_t)D_ * H_ * D_V);
    cudaEventRecord(ctx.eWo, s3);

    // s2: convert Wqa + Wkva into wcomb (concurrent with x convert on s0)
    launch_cvt_s(s2, Wqa,  wcomb, (size_t)Q_LORA * D_);
    launch_cvt_s(s2, Wkva, wcomb + (size_t)Q_LORA * D_, (size_t)(KV_LORA + D_ROPE) * D_);
    cudaEventRecord(ctx.eWc, s2);

    // s0: convert x, then GEMM1 (writes proj1 + rotated kpe) + fused RMSNorms
    launch_cvt_s(s0, x, xh, (size_t)BS * D_);
    cudaStreamWaitEvent(s0, ctx.eWc, 0);
    // 1. proj1 = x @ [Wqa;Wkva]^T          [4096,2112] K=2048 -> half (+ kpe rotated)
    launch_gemm_s(s0, xh, wcomb, proj1, BS, NPROJ1, D_, D_, D_, NPROJ1,
                  1.0f, HOUT | ROPEK, freqs, kpe);
    // 2. fused RMSNorms -> half
    rmsnorm2_kernel<<<dim3(BS, 2), 256, 0, s0>>>(proj1, qlnw, kvlnw, qan, kvc);
    cudaEventRecord(ctx.eN, s0);

    // s2: GEMM4 (needs kvc from eN + wkvbh from eW2)
    cudaStreamWaitEvent(s2, ctx.eN, 0);
    cudaStreamWaitEvent(s2, ctx.eW2, 0);
    // 4. kv_b = kv_c @ Wkvb^T              [4096,4096] K=512 -> half
    launch_gemm_s(s2, kvc, wkvbh, kvb, BS, H_ * (D_NOPE + D_V), KV_LORA, KV_LORA, KV_LORA,
                  H_ * (D_NOPE + D_V), 1.0f, HOUT);
    cudaEventRecord(ctx.e4, s2);

    // s0: GEMM3 (needs wqbh from eW), RoPE applied in epilogue, concurrent with GEMM4
    cudaStreamWaitEvent(s0, ctx.eW, 0);
    // 3. q_full = q_a_n @ Wqb^T            [4096,3072] K=1536 -> half, pe cols rotated
    launch_gemm_s(s0, qan, wqbh, qfull, BS, H_ * D_QK, Q_LORA, Q_LORA, Q_LORA, H_ * D_QK,
                  1.0f, HOUT | ROPEQ, freqs, nullptr);

    // join: flash needs GEMM4 output (kvb); qfull/kpe already ordered on s0
    cudaStreamWaitEvent(s0, ctx.e4, 0);
    // 6. fused flash attention -> attn (half)
    flash_kernel<<<dim3(S_ / 128, BH), 256, FSMEM, s0>>>(qfull, kvb, kpe, attn, SCALE);
    // 7. out = attn @ Wo^T                 [4096,2048] K=2048 -> fp32
    cudaStreamWaitEvent(s0, ctx.eWo, 0);
    launch_gemm_s(s0, attn, woh, out, BS, D_, H_ * D_V, H_ * D_V, H_ * D_V, D_, 1.0f, 0);
}

// round 16
// speedup vs baseline: 1.0146x; 1.0146x over previous
#include <cuda_runtime.h>
#include <cuda.h>
#include <cuda_fp16.h>
#include <math.h>
#include <cstdint>

// ---------------- problem constants ----------------
constexpr int B_ = 2;
constexpr int S_ = 2048;
constexpr int D_ = 2048;
constexpr int H_ = 16;
constexpr int Q_LORA = 1536;
constexpr int KV_LORA = 512;
constexpr int D_NOPE = 128;
constexpr int D_ROPE = 64;
constexpr int D_QK = D_NOPE + D_ROPE;   // 192
constexpr int D_V = 128;
constexpr int BS = B_ * S_;             // 4096
constexpr int BH = B_ * H_;             // 32
constexpr int NPROJ1 = Q_LORA + KV_LORA + D_ROPE;   // 2112

// ---------------- scratch (device globals) ----------------
__device__ __half g_proj1[(size_t)BS * NPROJ1];            // [q_a | kv_c_raw | k_pe_raw] (half)
__device__ __half g_xh   [(size_t)BS * D_];
__device__ __half g_wcomb[(size_t)NPROJ1 * D_];            // [Wqa ; Wkva]
__device__ __half g_wqbh [(size_t)H_ * D_QK * Q_LORA];
__device__ __half g_wkvbh[(size_t)H_ * (D_NOPE + D_V) * KV_LORA];
__device__ __half g_woh  [(size_t)D_ * H_ * D_V];
__device__ __half g_qan  [(size_t)BS * Q_LORA];
__device__ __half g_kvc  [(size_t)BS * KV_LORA];
__device__ __half g_qfull[(size_t)BS * (H_ * D_QK)];       // RoPE applied in epilogue
__device__ __half g_kvb  [(size_t)BS * (H_ * (D_NOPE + D_V))];
__device__ __half g_kpe  [(size_t)BS * D_ROPE];            // roped k_pe (shared across heads)
__device__ __half g_attn [(size_t)BS * (H_ * D_V)];

// ---------------- PTX helpers ----------------
__device__ __forceinline__ void mma_f16(float* c, const uint32_t* a, uint32_t b0, uint32_t b1) {
    asm volatile(
        "mma.sync.aligned.m16n8k16.row.col.f32.f16.f16.f32 "
        "{%0,%1,%2,%3}, {%4,%5,%6,%7}, {%8,%9}, {%0,%1,%2,%3};"
        : "+f"(c[0]), "+f"(c[1]), "+f"(c[2]), "+f"(c[3])
        : "r"(a[0]), "r"(a[1]), "r"(a[2]), "r"(a[3]), "r"(b0), "r"(b1));
}
__device__ __forceinline__ void ldsm4(uint32_t* r, uint32_t addr) {
    asm volatile("ldmatrix.sync.aligned.m8n8.x4.shared.b16 {%0,%1,%2,%3}, [%4];"
                 : "=r"(r[0]), "=r"(r[1]), "=r"(r[2]), "=r"(r[3]) : "r"(addr));
}
__device__ __forceinline__ void ldsm4t(uint32_t* r, uint32_t addr) {
    asm volatile("ldmatrix.sync.aligned.m8n8.x4.trans.shared.b16 {%0,%1,%2,%3}, [%4];"
                 : "=r"(r[0]), "=r"(r[1]), "=r"(r[2]), "=r"(r[3]) : "r"(addr));
}
__device__ __forceinline__ void cp16(uint32_t dst, const void* src, int bytes) {
    asm volatile("cp.async.cg.shared.global [%0], [%1], 16, %2;"
                 :: "r"(dst), "l"(src), "r"(bytes));
}
#define CP_COMMIT() asm volatile("cp.async.commit_group;" ::: "memory")
#define CP_WAIT(n)  asm volatile("cp.async.wait_group %0;" :: "n"(n) : "memory")

__device__ __forceinline__ uint32_t h2u(float a, float b) {
    __half2 h = __floats2half2_rn(a, b);
    return *(uint32_t*)&h;
}

// ---------------- fp16 mma.sync GEMM, cp.async 3-stage, compile-time flags ----------------
// C[M,N] = alpha * A[M,K] * B[N,K]^T.
// FLAGS bit2 (HOUT): C is __half.   bit3 (ROPEQ): rotate pe cols (gn%192>=128).
// FLAGS bit4 (ROPEK): for gn>=2048 write rotated pair into kpe.
#define STAGES   3
#define TILE_B   16384
#define STAGE_B  (2 * TILE_B)
#define SMEM_BYTES (STAGES * STAGE_B)     // 98304

template <int FLAGS>
__global__ void __launch_bounds__(256, 2) gemm_h(
    const __half* __restrict__ A, const __half* __restrict__ Bm, void* __restrict__ Cv,
    int M, int N, int K, int lda, int ldb, int ldc,
    float alpha, const float* __restrict__ freqs, __half* __restrict__ kpe)
{
    extern __shared__ __align__(16) char smc[];
    int t = threadIdx.x;
    int wid = t >> 5, lane = t & 31;
    int wm = wid & 3;
    int wn = wid >> 2;
    int lr = lane >> 2, lc = lane & 3;

    int m0 = blockIdx.y * 128;
    int n0 = blockIdx.x * 128;
    int NK = K >> 6;

    const __half* Abase = A + (long long)m0 * lda;
    const __half* Bbase = Bm + (long long)n0 * ldb;
    int nvB = N - n0; if (nvB > 128) nvB = 128;

    uint32_t sb = (uint32_t)__cvta_generic_to_shared(smc);

    int crow[4], ckc[4];
    uint32_t cdst[4];
#pragma unroll
    for (int i = 0; i < 4; i++) {
        int idx = t + i * 256;
        crow[i] = idx >> 3;
        ckc[i]  = idx & 7;
        cdst[i] = (uint32_t)(crow[i] * 128 + ((ckc[i] ^ (crow[i] & 7)) << 4));
    }

    auto issue = [&](int stage, int k0) {
        uint32_t dA = sb + (uint32_t)(stage * STAGE_B);
        uint32_t dB = dA + TILE_B;
#pragma unroll
        for (int i = 0; i < 4; i++) {
            int row = crow[i];
            cp16(dA + cdst[i], Abase + (long long)row * lda + k0 + ckc[i] * 8, 16);
            int brow = (row < nvB) ? row : 0;
            cp16(dB + cdst[i], Bbase + (long long)brow * ldb + k0 + ckc[i] * 8,
                 (row < nvB) ? 16 : 0);
        }
    };

    int aRow0 = wm * 32 + (lane & 15);
    int aSel  = (lane >> 4) & 1;
    int bRow0 = wn * 64 + (lane & 7) + (((lane >> 4) & 1) << 3);
    int bSel  = (lane >> 3) & 1;

    float acc[2][8][4];
#pragma unroll
    for (int i = 0; i < 2; i++)
#pragma unroll
        for (int j = 0; j < 8; j++)
#pragma unroll
            for (int k = 0; k < 4; k++) acc[i][j][k] = 0.f;

    issue(0, 0); CP_COMMIT();
    if (NK > 1) issue(1, 64);
    CP_COMMIT();
    int fetch = 2;

    for (int kt = 0; kt < NK; kt++) {
        CP_WAIT(1);
        __syncthreads();
        if (fetch < NK) issue(fetch % STAGES, fetch << 6);
        CP_COMMIT();
        fetch++;

        uint32_t sA = sb + (uint32_t)((kt % STAGES) * STAGE_B);
        uint32_t sB = sA + TILE_B;
#pragma unroll
        for (int ks = 0; ks < 4; ks++) {
            uint32_t a[2][4];
#pragma unroll
            for (int mf = 0; mf < 2; mf++) {
                int row = aRow0 + mf * 16;
                uint32_t addr = sA + row * 128 + ((((ks << 1) | aSel) ^ (row & 7)) << 4);
                ldsm4(a[mf], addr);
            }
#pragma unroll
            for (int nf2 = 0; nf2 < 4; nf2++) {
                int row = bRow0 + nf2 * 16;
                uint32_t addr = sB + row * 128 + ((((ks << 1) | bSel) ^ (row & 7)) << 4);
                uint32_t b[4];
                ldsm4(b, addr);
                mma_f16(acc[0][2 * nf2],     a[0], b[0], b[1]);
                mma_f16(acc[1][2 * nf2],     a[1], b[0], b[1]);
                mma_f16(acc[0][2 * nf2 + 1], a[0], b[2], b[3]);
                mma_f16(acc[1][2 * nf2 + 1], a[1], b[2], b[3]);
            }
        }
    }

#pragma unroll
    for (int mf = 0; mf < 2; mf++) {
        int r0 = m0 + wm * 32 + mf * 16 + lr;
#pragma unroll
        for (int nf = 0; nf < 8; nf++) {
            int gn = n0 + wn * 64 + nf * 8 + 2 * lc;
            if (gn < N) {
                float v0 = alpha * acc[mf][nf][0], v1 = alpha * acc[mf][nf][1];
                float v2 = alpha * acc[mf][nf][2], v3 = alpha * acc[mf][nf][3];
                if constexpr ((FLAGS & 8) != 0) {        // ROPEQ
                    int d = gn % D_QK;
                    if (d >= D_NOPE) {
                        int p2 = d - D_NOPE;
                        {
                            const float* fr = freqs + (long long)(r0 & (S_ - 1)) * D_ROPE + p2;
                            float c = fr[0], sn = fr[1];
                            float t0 = v0 * c - v1 * sn, t1 = v0 * sn + v1 * c;
                            v0 = t0; v1 = t1;
                        }
                        {
                            const float* fr = freqs + (long long)((r0 + 8) & (S_ - 1)) * D_ROPE + p2;
                            float c = fr[0], sn = fr[1];
                            float t2 = v2 * c - v3 * sn, t3 = v2 * sn + v3 * c;
                            v2 = t2; v3 = t3;
                        }
                    }
                }
                if constexpr ((FLAGS & 16) != 0) {       // ROPEK
                    if (gn >= (Q_LORA + KV_LORA)) {
                        int p2 = gn - (Q_LORA + KV_LORA);
                        {
                            const float* fr = freqs + (long long)(r0 & (S_ - 1)) * D_ROPE + p2;
                            float c = fr[0], sn = fr[1];
                            *(__half2*)(kpe + (long long)r0 * D_ROPE + p2) =
                                __floats2half2_rn(v0 * c - v1 * sn, v0 * sn + v1 * c);
                        }
                        {
                            const float* fr = freqs + (long long)((r0 + 8) & (S_ - 1)) * D_ROPE + p2;
                            float c = fr[0], sn = fr[1];
                            *(__half2*)(kpe + (long long)(r0 + 8) * D_ROPE + p2) =
                                __floats2half2_rn(v2 * c - v3 * sn, v2 * sn + v3 * c);
                        }
                    }
                }
                if constexpr ((FLAGS & 4) != 0) {
                    __half* C = (__half*)Cv;
                    *(__half2*)(C + (long long)r0 * ldc + gn) = __floats2half2_rn(v0, v1);
                    *(__half2*)(C + (long long)(r0 + 8) * ldc + gn) = __floats2half2_rn(v2, v3);
                } else {
                    float* C = (float*)Cv;
                    *(float2*)(C + (long long)r0 * ldc + gn) = make_float2(v0, v1);
                    *(float2*)(C + (long long)(r0 + 8) * ldc + gn) = make_float2(v2, v3);
                }
            }
        }
    }
}

// ---------------- fused flash attention (validated R11-R15, unchanged) ----------------
#define FQ_B  49152
#define FK_B  49152
#define FV_B  32768
#define FSMEM (FQ_B + 2 * FK_B + 2 * FV_B)    // 212992

__global__ void __launch_bounds__(256, 1) flash_kernel(
    const __half* __restrict__ qfull, const __half* __restrict__ kvb,
    const __half* __restrict__ kpe, __half* __restrict__ attn, float scale)
{
    extern __shared__ __align__(16) char sm[];
    int t = threadIdx.x, wid = t >> 5, lane = t & 31;
    int qt = (int)gridDim.x - 1 - (int)blockIdx.x;     // longest tiles first
    int bh = blockIdx.y;
    int b = bh >> 4, h = bh & 15;
    int q0 = qt * 128;
    int wrow = wid * 16;
    int lr = lane >> 2, lc = lane & 3;

    const __half* Qg = qfull + ((long long)(b * S_ + q0) * H_ + h) * D_QK;
    const __half* Kn = kvb + ((long long)(b * S_) * H_ + h) * 256;
    const __half* Pe = kpe + (long long)b * S_ * D_ROPE;

    uint32_t sb = (uint32_t)__cvta_generic_to_shared(sm);
    uint32_t sQ  = sb;
    uint32_t sK0 = sb + FQ_B;
    uint32_t sV0 = sb + FQ_B + 2 * FK_B;

#pragma unroll
    for (int i = 0; i < 12; i++) {
        int c = i * 256 + t;
        int row = c / 24, ch = c % 24;
        uint32_t sw = (uint32_t)((ch & ~7) | ((ch & 7) ^ (row & 7)));
        cp16(sQ + row * 384 + sw * 16, Qg + (long long)row * (H_ * D_QK) + ch * 8, 16);
    }
    CP_COMMIT();

    auto issueKV = [&](int kt2, int buf2) {
        uint32_t dK = sK0 + (uint32_t)buf2 * FK_B;
        uint32_t dV = sV0 + (uint32_t)buf2 * FV_B;
        const __half* Ks = Kn + (long long)(kt2 * 128) * (H_ * 256);
        const __half* Ps = Pe + (long long)(kt2 * 128) * D_ROPE;
#pragma unroll
        for (int i = 0; i < 12; i++) {
            int c = i * 256 + t;
            int row = c / 24, ch = c % 24;
            uint32_t sw = (uint32_t)((ch & ~7) | ((ch & 7) ^ (row & 7)));
            const __half* src = (ch < 16)
                ? (Ks + (long long)row * (H_ * 256) + ch * 8)
                : (Ps + row * D_ROPE + (ch - 16) * 8);
            cp16(dK + row * 384 + sw * 16, src, 16);
        }
#pragma unroll
        for (int i = 0; i < 8; i++) {
            int c = i * 256 + t;
            int row = c >> 4, ch = c & 15;
            uint32_t sw = (uint32_t)((ch & ~7) | ((ch & 7) ^ (row & 7)));
            cp16(dV + row * 256 + sw * 16,
                 Ks + (long long)row * (H_ * 256) + 128 + ch * 8, 16);
        }
    };

    issueKV(0, 0); CP_COMMIT();

    float o[16][4];
#pragma unroll
    for (int i = 0; i < 16; i++)
#pragma unroll
        for (int j = 0; j < 4; j++) o[i][j] = 0.f;
    float m0 = -1e30f, m1 = -1e30f, l0 = 0.f, l1 = 0.f;

    int aSel = (lane >> 4) & 1;
    int bSub = (lane & 7) + (((lane >> 4) & 1) << 3);
    int bSel = (lane >> 3) & 1;
    int vs_lane = lane & 15;
    int vd_half = (lane >> 4) & 1;

    for (int kt = 0; kt <= qt; kt++) {
        int buf = kt & 1;
        if (kt < qt) { issueKV(kt + 1, buf ^ 1); CP_COMMIT(); CP_WAIT(1); }
        else         { CP_WAIT(0); }
        __syncthreads();

        uint32_t sK = sK0 + (uint32_t)buf * FK_B;
        uint32_t sV = sV0 + (uint32_t)buf * FV_B;

        float s[16][4];
#pragma unroll
        for (int i = 0; i < 16; i++)
#pragma unroll
            for (int j = 0; j < 4; j++) s[i][j] = 0.f;
#pragma unroll
        for (int ks = 0; ks < 12; ks++) {
            uint32_t a[4];
            {
                int r = wrow + (lane & 15);
                int ch = 2 * ks + aSel;
                uint32_t sw = (uint32_t)((ch & ~7) | ((ch & 7) ^ (r & 7)));
                ldsm4(a, sQ + r * 384 + sw * 16);
            }
#pragma unroll
            for (int nf2 = 0; nf2 < 8; nf2++) {
                int r = nf2 * 16 + bSub;
                int ch = 2 * ks + bSel;
                uint32_t sw = (uint32_t)((ch & ~7) | ((ch & 7) ^ (r & 7)));
                uint32_t bf[4];
                ldsm4(bf, sK + r * 384 + sw * 16);
                mma_f16(s[2 * nf2],     a, bf[0], bf[1]);
                mma_f16(s[2 * nf2 + 1], a, bf[2], bf[3]);
            }
        }

#pragma unroll
        for (int nf = 0; nf < 16; nf++)
#pragma unroll
            for (int j = 0; j < 4; j++) s[nf][j] *= scale;
        if (kt == qt) {
            int row0 = q0 + wrow + lr;
            int colb = q0 + 2 * lc;
#pragma unroll
            for (int nf = 0; nf < 16; nf++) {
                int c0 = colb + nf * 8;
                if (c0 > row0)         s[nf][0] = -1e30f;
                if (c0 + 1 > row0)     s[nf][1] = -1e30f;
                if (c0 > row0 + 8)     s[nf][2] = -1e30f;
                if (c0 + 1 > row0 + 8) s[nf][3] = -1e30f;
            }
        }

        float mx0 = -1e30f, mx1 = -1e30f;
#pragma unroll
        for (int nf = 0; nf < 16; nf++) {
            mx0 = fmaxf(mx0, fmaxf(s[nf][0], s[nf][1]));
            mx1 = fmaxf(mx1, fmaxf(s[nf][2], s[nf][3]));
        }
        mx0 = fmaxf(mx0, __shfl_xor_sync(0xffffffffu, mx0, 1));
        mx0 = fmaxf(mx0, __shfl_xor_sync(0xffffffffu, mx0, 2));
        mx1 = fmaxf(mx1, __shfl_xor_sync(0xffffffffu, mx1, 1));
        mx1 = fmaxf(mx1, __shfl_xor_sync(0xffffffffu, mx1, 2));
        float mn0 = fmaxf(m0, mx0), mn1 = fmaxf(m1, mx1);
        float al0 = __expf(m0 - mn0), al1 = __expf(m1 - mn1);
        m0 = mn0; m1 = mn1;
        float sum0 = 0.f, sum1 = 0.f;
#pragma unroll
        for (int nf = 0; nf < 16; nf++) {
            float p0 = __expf(s[nf][0] - mn0);
            float p1 = __expf(s[nf][1] - mn0);
            float p2 = __expf(s[nf][2] - mn1);
            float p3 = __expf(s[nf][3] - mn1);
            s[nf][0] = p0; s[nf][1] = p1; s[nf][2] = p2; s[nf][3] = p3;
            sum0 += p0 + p1; sum1 += p2 + p3;
        }
        sum0 += __shfl_xor_sync(0xffffffffu, sum0, 1);
        sum0 += __shfl_xor_sync(0xffffffffu, sum0, 2);
        sum1 += __shfl_xor_sync(0xffffffffu, sum1, 1);
        sum1 += __shfl_xor_sync(0xffffffffu, sum1, 2);
        l0 = l0 * al0 + sum0;
        l1 = l1 * al1 + sum1;
#pragma unroll
        for (int nf = 0; nf < 16; nf++) {
            o[nf][0] *= al0; o[nf][1] *= al0;
            o[nf][2] *= al1; o[nf][3] *= al1;
        }

#pragma unroll
        for (int j = 0; j < 8; j++) {
            uint32_t pa[4];
            pa[0] = h2u(s[2 * j][0],     s[2 * j][1]);
            pa[1] = h2u(s[2 * j][2],     s[2 * j][3]);
            pa[2] = h2u(s[2 * j + 1][0], s[2 * j + 1][1]);
            pa[3] = h2u(s[2 * j + 1][2], s[2 * j + 1][3]);
            int s_off = 16 * j + vs_lane;
#pragma unroll
            for (int nd2 = 0; nd2 < 8; nd2++) {
                int d_chunk = nd2 * 2 + vd_half;
                uint32_t sw = (uint32_t)((d_chunk & ~7) | ((d_chunk & 7) ^ (s_off & 7)));
                uint32_t bf[4];
                ldsm4t(bf, sV + s_off * 256 + sw * 16);
                mma_f16(o[2 * nd2],     pa, bf[0], bf[1]);
                mma_f16(o[2 * nd2 + 1], pa, bf[2], bf[3]);
            }
        }
        __syncthreads();
    }

    float il0 = 1.f / l0, il1 = 1.f / l1;
    int sg = q0 + wrow + lr;
    __half* a0 = attn + ((long long)(b * S_ + sg) * (H_ * D_V)) + h * D_V;
    __half* a1 = a0 + (long long)8 * (H_ * D_V);
#pragma unroll
    for (int nf = 0; nf < 16; nf++) {
        int d = nf * 8 + 2 * lc;
        *(__half2*)(a0 + d) = __floats2half2_rn(o[nf][0] * il0, o[nf][1] * il0);
        *(__half2*)(a1 + d) = __floats2half2_rn(o[nf][2] * il1, o[nf][3] * il1);
    }
}

// ---------------- fp32 -> fp16 convert ----------------
__global__ void cvt_f2h_kernel(const float* __restrict__ in, __half* __restrict__ out, int n4)
{
    int i = blockIdx.x * blockDim.x + threadIdx.x;
    int stride = gridDim.x * blockDim.x;
    for (; i < n4; i += stride) {
        float4 v = ((const float4*)in)[i];
        __half2 h0 = __floats2half2_rn(v.x, v.y);
        __half2 h1 = __floats2half2_rn(v.z, v.w);
        *(uint2*)(out + (size_t)i * 4) = make_uint2(*(uint32_t*)&h0, *(uint32_t*)&h1);
    }
}

// ---------------- fused dual RMSNorm (half in strided, half out) ----------------
__global__ void rmsnorm2_kernel(const __half* __restrict__ proj1,
                                const float* __restrict__ qw, const float* __restrict__ kw,
                                __half* __restrict__ qan, __half* __restrict__ kvc)
{
    long long row = blockIdx.x;
    int which = blockIdx.y;
    int width = which ? KV_LORA : Q_LORA;
    const __half* x = proj1 + row * NPROJ1 + (which ? Q_LORA : 0);
    const float* w = which ? kw : qw;
    __half* o = which ? (kvc + row * KV_LORA) : (qan + row * Q_LORA);
    __shared__ float red[256];
    int t = threadIdx.x;
    float ss = 0.f;
    for (int i = t; i < width; i += 256) { float v = __half2float(x[i]); ss += v * v; }
    red[t] = ss;
    __syncthreads();
    for (int s = 128; s > 0; s >>= 1) {
        if (t < s) red[t] += red[t + s];
        __syncthreads();
    }
    float scale = rsqrtf(red[0] / (float)width + 1e-6f);
    for (int i = t; i < width; i += 256)
        o[i] = __float2half_rn(__half2float(x[i]) * scale * w[i]);
}

// ---------------- launch helpers ----------------
template <int FLAGS>
static void launch_gemm_t(cudaStream_t st, const __half* A, const __half* Bm, void* C,
                          int M, int N, int K, int lda, int ldb, int ldc,
                          float alpha, const float* freqs = nullptr, __half* kpe = nullptr)
{
    dim3 grid((N + 127) / 128, (M + 127) / 128, 1);
    gemm_h<FLAGS><<<grid, 256, SMEM_BYTES, st>>>(A, Bm, C, M, N, K, lda, ldb, ldc,
                                                 alpha, freqs, kpe);
}

static void launch_cvt_s(cudaStream_t st, const float* in, __half* out, size_t n)
{
    int n4 = (int)(n / 4);
    int blocks = (n4 + 255) / 256;
    if (blocks > 8192) blocks = 8192;
    cvt_f2h_kernel<<<blocks, 256, 0, st>>>(in, out, n4);
}

// ---- lazily-initialized streams/events (created ONCE on first call = part of
// the harness's pre-capture baseline; no per-call allocation) ----
struct StreamCtx {
    cudaStream_t s2, s3;
    cudaEvent_t eFork, eWc, eW, eW2, eWo, eN, e4;
    StreamCtx() {
        cudaStreamCreateWithFlags(&s2, cudaStreamNonBlocking);
        cudaStreamCreateWithFlags(&s3, cudaStreamNonBlocking);
        cudaEventCreateWithFlags(&eFork, cudaEventDisableTiming);
        cudaEventCreateWithFlags(&eWc,   cudaEventDisableTiming);
        cudaEventCreateWithFlags(&eW,    cudaEventDisableTiming);
        cudaEventCreateWithFlags(&eW2,   cudaEventDisableTiming);
        cudaEventCreateWithFlags(&eWo,   cudaEventDisableTiming);
        cudaEventCreateWithFlags(&eN,    cudaEventDisableTiming);
        cudaEventCreateWithFlags(&e4,    cudaEventDisableTiming);
    }
};

extern "C" void kernel_launch(void* const* d_in, const int* in_sizes, int n_in,
                              void* d_out, int out_size)
{
    const float* x     = (const float*)d_in[0];
    const float* freqs = (const float*)d_in[1];
    const float* Wqa   = (const float*)d_in[2];
    const float* qlnw  = (const float*)d_in[3];
    const float* Wqb   = (const float*)d_in[4];
    const float* Wkva  = (const float*)d_in[5];
    const float* kvlnw = (const float*)d_in[6];
    const float* Wkvb  = (const float*)d_in[7];
    const float* Wo    = (const float*)d_in[8];
    float* out = (float*)d_out;

    const int HOUT = 4, ROPEQ = 8, ROPEK = 16;
    cudaFuncSetAttribute(gemm_h<HOUT | ROPEK>, cudaFuncAttributeMaxDynamicSharedMemorySize, SMEM_BYTES);
    cudaFuncSetAttribute(gemm_h<HOUT | ROPEQ>, cudaFuncAttributeMaxDynamicSharedMemorySize, SMEM_BYTES);
    cudaFuncSetAttribute(gemm_h<HOUT>,         cudaFuncAttributeMaxDynamicSharedMemorySize, SMEM_BYTES);
    cudaFuncSetAttribute(gemm_h<0>,            cudaFuncAttributeMaxDynamicSharedMemorySize, SMEM_BYTES);
    cudaFuncSetAttribute(flash_kernel, cudaFuncAttributeMaxDynamicSharedMemorySize, FSMEM);

    __half *proj1, *xh, *wcomb, *wqbh, *wkvbh, *woh;
    __half *qan, *kvc, *qfull, *kvb, *kpe, *attn;
    cudaGetSymbolAddress((void**)&proj1,  g_proj1);
    cudaGetSymbolAddress((void**)&xh,     g_xh);
    cudaGetSymbolAddress((void**)&wcomb,  g_wcomb);
    cudaGetSymbolAddress((void**)&wqbh,   g_wqbh);
    cudaGetSymbolAddress((void**)&wkvbh,  g_wkvbh);
    cudaGetSymbolAddress((void**)&woh,    g_woh);
    cudaGetSymbolAddress((void**)&qan,    g_qan);
    cudaGetSymbolAddress((void**)&kvc,    g_kvc);
    cudaGetSymbolAddress((void**)&qfull,  g_qfull);
    cudaGetSymbolAddress((void**)&kvb,    g_kvb);
    cudaGetSymbolAddress((void**)&kpe,    g_kpe);
    cudaGetSymbolAddress((void**)&attn,   g_attn);

    const float SCALE = 1.0f / sqrtf((float)D_QK);
    cudaStream_t s0 = 0;

    static StreamCtx ctx;          // created once on first (correctness) call
    cudaStream_t s2 = ctx.s2, s3 = ctx.s3;

    // fork s2/s3 off the capture (NULL) stream
    cudaEventRecord(ctx.eFork, s0);
    cudaStreamWaitEvent(s2, ctx.eFork, 0);
    cudaStreamWaitEvent(s3, ctx.eFork, 0);

    // s3: weight converts for later GEMMs
    launch_cvt_s(s3, Wqb,  wqbh,  (size_t)H_ * D_QK * Q_LORA);
    cudaEventRecord(ctx.eW, s3);
    launch_cvt_s(s3, Wkvb, wkvbh, (size_t)H_ * (D_NOPE + D_V) * KV_LORA);
    cudaEventRecord(ctx.eW2, s3);
    launch_cvt_s(s3, Wo,   woh,   (size_t)D_ * H_ * D_V);
    cudaEventRecord(ctx.eWo, s3);

    // s2: convert Wqa + Wkva into wcomb (concurrent with x convert on s0)
    launch_cvt_s(s2, Wqa,  wcomb, (size_t)Q_LORA * D_);
    launch_cvt_s(s2, Wkva, wcomb + (size_t)Q_LORA * D_, (size_t)(KV_LORA + D_ROPE) * D_);
    cudaEventRecord(ctx.eWc, s2);

    // s0: convert x, then GEMM1 (writes proj1 + rotated kpe) + fused RMSNorms
    launch_cvt_s(s0, x, xh, (size_t)BS * D_);
    cudaStreamWaitEvent(s0, ctx.eWc, 0);
    // 1. proj1 = x @ [Wqa;Wkva]^T          [4096,2112] K=2048 -> half (+ kpe rotated)
    launch_gemm_t<HOUT | ROPEK>(s0, xh, wcomb, proj1, BS, NPROJ1, D_, D_, D_, NPROJ1,
                                1.0f, freqs, kpe);
    // 2. fused RMSNorms -> half
    rmsnorm2_kernel<<<dim3(BS, 2), 256, 0, s0>>>(proj1, qlnw, kvlnw, qan, kvc);
    cudaEventRecord(ctx.eN, s0);

    // s2: GEMM4 (needs kvc from eN + wkvbh from eW2)
    cudaStreamWaitEvent(s2, ctx.eN, 0);
    cudaStreamWaitEvent(s2, ctx.eW2, 0);
    // 4. kv_b = kv_c @ Wkvb^T              [4096,4096] K=512 -> half
    launch_gemm_t<HOUT>(s2, kvc, wkvbh, kvb, BS, H_ * (D_NOPE + D_V), KV_LORA,
                        KV_LORA, KV_LORA, H_ * (D_NOPE + D_V), 1.0f);
    cudaEventRecord(ctx.e4, s2);

    // s0: GEMM3 (needs wqbh from eW), RoPE applied in epilogue, concurrent with GEMM4
    cudaStreamWaitEvent(s0, ctx.eW, 0);
    // 3. q_full = q_a_n @ Wqb^T            [4096,3072] K=1536 -> half, pe cols rotated
    launch_gemm_t<HOUT | ROPEQ>(s0, qan, wqbh, qfull, BS, H_ * D_QK, Q_LORA,
                                Q_LORA, Q_LORA, H_ * D_QK, 1.0f, freqs, nullptr);

    // join: flash needs GEMM4 output (kvb); qfull/kpe already ordered on s0
    cudaStreamWaitEvent(s0, ctx.e4, 0);
    // 6. fused flash attention -> attn (half)
    flash_kernel<<<dim3(S_ / 128, BH), 256, FSMEM, s0>>>(qfull, kvb, kpe, attn, SCALE);
    // 7. out = attn @ Wo^T                 [4096,2048] K=2048 -> fp32
    cudaStreamWaitEvent(s0, ctx.eWo, 0);
    launch_gemm_t<0>(s0, attn, woh, out, BS, D_, H_ * D_V, H_ * D_V, H_ * D_V, D_, 1.0f);
}

// round 17
// speedup vs baseline: 1.0298x; 1.0149x over previous
#include <cuda_runtime.h>
#include <cuda.h>
#include <cuda_fp16.h>
#include <math.h>
#include <cstdint>

// ---------------- problem constants ----------------
constexpr int B_ = 2;
constexpr int S_ = 2048;
constexpr int D_ = 2048;
constexpr int H_ = 16;
constexpr int Q_LORA = 1536;
constexpr int KV_LORA = 512;
constexpr int D_NOPE = 128;
constexpr int D_ROPE = 64;
constexpr int D_QK = D_NOPE + D_ROPE;   // 192
constexpr int D_V = 128;
constexpr int BS = B_ * S_;             // 4096
constexpr int BH = B_ * H_;             // 32
constexpr int NPROJ1 = Q_LORA + KV_LORA + D_ROPE;   // 2112

// ---------------- scratch (device globals) ----------------
__device__ __half g_proj1[(size_t)BS * NPROJ1];            // [q_a | kv_c_raw | k_pe_raw] (half)
__device__ __half g_xh   [(size_t)BS * D_];
__device__ __half g_wcomb[(size_t)NPROJ1 * D_];            // [Wqa ; Wkva]
__device__ __half g_wqbh [(size_t)H_ * D_QK * Q_LORA];
__device__ __half g_wkvbh[(size_t)H_ * (D_NOPE + D_V) * KV_LORA];
__device__ __half g_woh  [(size_t)D_ * H_ * D_V];
__device__ __half g_qan  [(size_t)BS * Q_LORA];
__device__ __half g_kvc  [(size_t)BS * KV_LORA];
__device__ __half g_qfull[(size_t)BS * (H_ * D_QK)];       // RoPE applied in-place
__device__ __half g_kvb  [(size_t)BS * (H_ * (D_NOPE + D_V))];
__device__ __half g_kpe  [(size_t)BS * D_ROPE];            // roped k_pe (shared across heads)
__device__ __half g_attn [(size_t)BS * (H_ * D_V)];

// ---------------- PTX helpers ----------------
__device__ __forceinline__ void mma_f16(float* c, const uint32_t* a, uint32_t b0, uint32_t b1) {
    asm volatile(
        "mma.sync.aligned.m16n8k16.row.col.f32.f16.f16.f32 "
        "{%0,%1,%2,%3}, {%4,%5,%6,%7}, {%8,%9}, {%0,%1,%2,%3};"
        : "+f"(c[0]), "+f"(c[1]), "+f"(c[2]), "+f"(c[3])
        : "r"(a[0]), "r"(a[1]), "r"(a[2]), "r"(a[3]), "r"(b0), "r"(b1));
}
__device__ __forceinline__ void ldsm4(uint32_t* r, uint32_t addr) {
    asm volatile("ldmatrix.sync.aligned.m8n8.x4.shared.b16 {%0,%1,%2,%3}, [%4];"
                 : "=r"(r[0]), "=r"(r[1]), "=r"(r[2]), "=r"(r[3]) : "r"(addr));
}
__device__ __forceinline__ void ldsm4t(uint32_t* r, uint32_t addr) {
    asm volatile("ldmatrix.sync.aligned.m8n8.x4.trans.shared.b16 {%0,%1,%2,%3}, [%4];"
                 : "=r"(r[0]), "=r"(r[1]), "=r"(r[2]), "=r"(r[3]) : "r"(addr));
}
__device__ __forceinline__ void cp16(uint32_t dst, const void* src, int bytes) {
    asm volatile("cp.async.cg.shared.global [%0], [%1], 16, %2;"
                 :: "r"(dst), "l"(src), "r"(bytes));
}
#define CP_COMMIT() asm volatile("cp.async.commit_group;" ::: "memory")
#define CP_WAIT(n)  asm volatile("cp.async.wait_group %0;" :: "n"(n) : "memory")

__device__ __forceinline__ uint32_t h2u(float a, float b) {
    __half2 h = __floats2half2_rn(a, b);
    return *(uint32_t*)&h;
}

// ---------------- fp16 mma.sync GEMM, cp.async 3-stage (R12 codegen, verbatim) ----------------
// C[M,N] = alpha * A[M,K] * B[N,K]^T  flags bit2: C is __half.
#define STAGES   3
#define TILE_B   16384
#define STAGE_B  (2 * TILE_B)
#define SMEM_BYTES (STAGES * STAGE_B)     // 98304

__global__ void __launch_bounds__(256, 2) gemm_h(
    const __half* __restrict__ A, const __half* __restrict__ Bm, void* __restrict__ Cv,
    int M, int N, int K, int lda, int ldb, int ldc,
    float alpha, int flags)
{
    extern __shared__ __align__(16) char smc[];
    int t = threadIdx.x;
    int wid = t >> 5, lane = t & 31;
    int wm = wid & 3;
    int wn = wid >> 2;
    int lr = lane >> 2, lc = lane & 3;

    int m0 = blockIdx.y * 128;
    int n0 = blockIdx.x * 128;
    int NK = K >> 6;

    const __half* Abase = A + (long long)m0 * lda;
    const __half* Bbase = Bm + (long long)n0 * ldb;
    int nvB = N - n0; if (nvB > 128) nvB = 128;

    uint32_t sb = (uint32_t)__cvta_generic_to_shared(smc);

    int crow[4], ckc[4];
    uint32_t cdst[4];
#pragma unroll
    for (int i = 0; i < 4; i++) {
        int idx = t + i * 256;
        crow[i] = idx >> 3;
        ckc[i]  = idx & 7;
        cdst[i] = (uint32_t)(crow[i] * 128 + ((ckc[i] ^ (crow[i] & 7)) << 4));
    }

    auto issue = [&](int stage, int k0) {
        uint32_t dA = sb + (uint32_t)(stage * STAGE_B);
        uint32_t dB = dA + TILE_B;
#pragma unroll
        for (int i = 0; i < 4; i++) {
            int row = crow[i];
            cp16(dA + cdst[i], Abase + (long long)row * lda + k0 + ckc[i] * 8, 16);
            int brow = (row < nvB) ? row : 0;
            cp16(dB + cdst[i], Bbase + (long long)brow * ldb + k0 + ckc[i] * 8,
                 (row < nvB) ? 16 : 0);
        }
    };

    int aRow0 = wm * 32 + (lane & 15);
    int aSel  = (lane >> 4) & 1;
    int bRow0 = wn * 64 + (lane & 7) + (((lane >> 4) & 1) << 3);
    int bSel  = (lane >> 3) & 1;

    float acc[2][8][4];
#pragma unroll
    for (int i = 0; i < 2; i++)
#pragma unroll
        for (int j = 0; j < 8; j++)
#pragma unroll
            for (int k = 0; k < 4; k++) acc[i][j][k] = 0.f;

    issue(0, 0); CP_COMMIT();
    if (NK > 1) issue(1, 64);
    CP_COMMIT();
    int fetch = 2;

    for (int kt = 0; kt < NK; kt++) {
        CP_WAIT(1);
        __syncthreads();
        if (fetch < NK) issue(fetch % STAGES, fetch << 6);
        CP_COMMIT();
        fetch++;

        uint32_t sA = sb + (uint32_t)((kt % STAGES) * STAGE_B);
        uint32_t sB = sA + TILE_B;
#pragma unroll
        for (int ks = 0; ks < 4; ks++) {
            uint32_t a[2][4];
#pragma unroll
            for (int mf = 0; mf < 2; mf++) {
                int row = aRow0 + mf * 16;
                uint32_t addr = sA + row * 128 + ((((ks << 1) | aSel) ^ (row & 7)) << 4);
                ldsm4(a[mf], addr);
            }
#pragma unroll
            for (int nf2 = 0; nf2 < 4; nf2++) {
                int row = bRow0 + nf2 * 16;
                uint32_t addr = sB + row * 128 + ((((ks << 1) | bSel) ^ (row & 7)) << 4);
                uint32_t b[4];
                ldsm4(b, addr);
                mma_f16(acc[0][2 * nf2],     a[0], b[0], b[1]);
                mma_f16(acc[1][2 * nf2],     a[1], b[0], b[1]);
                mma_f16(acc[0][2 * nf2 + 1], a[0], b[2], b[3]);
                mma_f16(acc[1][2 * nf2 + 1], a[1], b[2], b[3]);
            }
        }
    }

    bool hout = (flags & 4) != 0;
#pragma unroll
    for (int mf = 0; mf < 2; mf++) {
        int r0 = m0 + wm * 32 + mf * 16 + lr;
#pragma unroll
        for (int nf = 0; nf < 8; nf++) {
            int gn = n0 + wn * 64 + nf * 8 + 2 * lc;
            if (gn < N) {
                float v0 = alpha * acc[mf][nf][0], v1 = alpha * acc[mf][nf][1];
                float v2 = alpha * acc[mf][nf][2], v3 = alpha * acc[mf][nf][3];
                if (hout) {
                    __half* C = (__half*)Cv;
                    *(__half2*)(C + (long long)r0 * ldc + gn) = __floats2half2_rn(v0, v1);
                    *(__half2*)(C + (long long)(r0 + 8) * ldc + gn) = __floats2half2_rn(v2, v3);
                } else {
                    float* C = (float*)Cv;
                    *(float2*)(C + (long long)r0 * ldc + gn) = make_float2(v0, v1);
                    *(float2*)(C + (long long)(r0 + 8) * ldc + gn) = make_float2(v2, v3);
                }
            }
        }
    }
}

// ---------------- fused flash attention (validated R11-R16, unchanged) ----------------
#define FQ_B  49152
#define FK_B  49152
#define FV_B  32768
#define FSMEM (FQ_B + 2 * FK_B + 2 * FV_B)    // 212992

__global__ void __launch_bounds__(256, 1) flash_kernel(
    const __half* __restrict__ qfull, const __half* __restrict__ kvb,
    const __half* __restrict__ kpe, __half* __restrict__ attn, float scale)
{
    extern __shared__ __align__(16) char sm[];
    int t = threadIdx.x, wid = t >> 5, lane = t & 31;
    int qt = (int)gridDim.x - 1 - (int)blockIdx.x;     // longest tiles first
    int bh = blockIdx.y;
    int b = bh >> 4, h = bh & 15;
    int q0 = qt * 128;
    int wrow = wid * 16;
    int lr = lane >> 2, lc = lane & 3;

    const __half* Qg = qfull + ((long long)(b * S_ + q0) * H_ + h) * D_QK;
    const __half* Kn = kvb + ((long long)(b * S_) * H_ + h) * 256;
    const __half* Pe = kpe + (long long)b * S_ * D_ROPE;

    uint32_t sb = (uint32_t)__cvta_generic_to_shared(sm);
    uint32_t sQ  = sb;
    uint32_t sK0 = sb + FQ_B;
    uint32_t sV0 = sb + FQ_B + 2 * FK_B;

#pragma unroll
    for (int i = 0; i < 12; i++) {
        int c = i * 256 + t;
        int row = c / 24, ch = c % 24;
        uint32_t sw = (uint32_t)((ch & ~7) | ((ch & 7) ^ (row & 7)));
        cp16(sQ + row * 384 + sw * 16, Qg + (long long)row * (H_ * D_QK) + ch * 8, 16);
    }
    CP_COMMIT();

    auto issueKV = [&](int kt2, int buf2) {
        uint32_t dK = sK0 + (uint32_t)buf2 * FK_B;
        uint32_t dV = sV0 + (uint32_t)buf2 * FV_B;
        const __half* Ks = Kn + (long long)(kt2 * 128) * (H_ * 256);
        const __half* Ps = Pe + (long long)(kt2 * 128) * D_ROPE;
#pragma unroll
        for (int i = 0; i < 12; i++) {
            int c = i * 256 + t;
            int row = c / 24, ch = c % 24;
            uint32_t sw = (uint32_t)((ch & ~7) | ((ch & 7) ^ (row & 7)));
            const __half* src = (ch < 16)
                ? (Ks + (long long)row * (H_ * 256) + ch * 8)
                : (Ps + row * D_ROPE + (ch - 16) * 8);
            cp16(dK + row * 384 + sw * 16, src, 16);
        }
#pragma unroll
        for (int i = 0; i < 8; i++) {
            int c = i * 256 + t;
            int row = c >> 4, ch = c & 15;
            uint32_t sw = (uint32_t)((ch & ~7) | ((ch & 7) ^ (row & 7)));
            cp16(dV + row * 256 + sw * 16,
                 Ks + (long long)row * (H_ * 256) + 128 + ch * 8, 16);
        }
    };

    issueKV(0, 0); CP_COMMIT();

    float o[16][4];
#pragma unroll
    for (int i = 0; i < 16; i++)
#pragma unroll
        for (int j = 0; j < 4; j++) o[i][j] = 0.f;
    float m0 = -1e30f, m1 = -1e30f, l0 = 0.f, l1 = 0.f;

    int aSel = (lane >> 4) & 1;
    int bSub = (lane & 7) + (((lane >> 4) & 1) << 3);
    int bSel = (lane >> 3) & 1;
    int vs_lane = lane & 15;
    int vd_half = (lane >> 4) & 1;

    for (int kt = 0; kt <= qt; kt++) {
        int buf = kt & 1;
        if (kt < qt) { issueKV(kt + 1, buf ^ 1); CP_COMMIT(); CP_WAIT(1); }
        else         { CP_WAIT(0); }
        __syncthreads();

        uint32_t sK = sK0 + (uint32_t)buf * FK_B;
        uint32_t sV = sV0 + (uint32_t)buf * FV_B;

        float s[16][4];
#pragma unroll
        for (int i = 0; i < 16; i++)
#pragma unroll
            for (int j = 0; j < 4; j++) s[i][j] = 0.f;
#pragma unroll
        for (int ks = 0; ks < 12; ks++) {
            uint32_t a[4];
            {
                int r = wrow + (lane & 15);
                int ch = 2 * ks + aSel;
                uint32_t sw = (uint32_t)((ch & ~7) | ((ch & 7) ^ (r & 7)));
                ldsm4(a, sQ + r * 384 + sw * 16);
            }
#pragma unroll
            for (int nf2 = 0; nf2 < 8; nf2++) {
                int r = nf2 * 16 + bSub;
                int ch = 2 * ks + bSel;
                uint32_t sw = (uint32_t)((ch & ~7) | ((ch & 7) ^ (r & 7)));
                uint32_t bf[4];
                ldsm4(bf, sK + r * 384 + sw * 16);
                mma_f16(s[2 * nf2],     a, bf[0], bf[1]);
                mma_f16(s[2 * nf2 + 1], a, bf[2], bf[3]);
            }
        }

#pragma unroll
        for (int nf = 0; nf < 16; nf++)
#pragma unroll
            for (int j = 0; j < 4; j++) s[nf][j] *= scale;
        if (kt == qt) {
            int row0 = q0 + wrow + lr;
            int colb = q0 + 2 * lc;
#pragma unroll
            for (int nf = 0; nf < 16; nf++) {
                int c0 = colb + nf * 8;
                if (c0 > row0)         s[nf][0] = -1e30f;
                if (c0 + 1 > row0)     s[nf][1] = -1e30f;
                if (c0 > row0 + 8)     s[nf][2] = -1e30f;
                if (c0 + 1 > row0 + 8) s[nf][3] = -1e30f;
            }
        }

        float mx0 = -1e30f, mx1 = -1e30f;
#pragma unroll
        for (int nf = 0; nf < 16; nf++) {
            mx0 = fmaxf(mx0, fmaxf(s[nf][0], s[nf][1]));
            mx1 = fmaxf(mx1, fmaxf(s[nf][2], s[nf][3]));
        }
        mx0 = fmaxf(mx0, __shfl_xor_sync(0xffffffffu, mx0, 1));
        mx0 = fmaxf(mx0, __shfl_xor_sync(0xffffffffu, mx0, 2));
        mx1 = fmaxf(mx1, __shfl_xor_sync(0xffffffffu, mx1, 1));
        mx1 = fmaxf(mx1, __shfl_xor_sync(0xffffffffu, mx1, 2));
        float mn0 = fmaxf(m0, mx0), mn1 = fmaxf(m1, mx1);
        float al0 = __expf(m0 - mn0), al1 = __expf(m1 - mn1);
        m0 = mn0; m1 = mn1;
        float sum0 = 0.f, sum1 = 0.f;
#pragma unroll
        for (int nf = 0; nf < 16; nf++) {
            float p0 = __expf(s[nf][0] - mn0);
            float p1 = __expf(s[nf][1] - mn0);
            float p2 = __expf(s[nf][2] - mn1);
            float p3 = __expf(s[nf][3] - mn1);
            s[nf][0] = p0; s[nf][1] = p1; s[nf][2] = p2; s[nf][3] = p3;
            sum0 += p0 + p1; sum1 += p2 + p3;
        }
        sum0 += __shfl_xor_sync(0xffffffffu, sum0, 1);
        sum0 += __shfl_xor_sync(0xffffffffu, sum0, 2);
        sum1 += __shfl_xor_sync(0xffffffffu, sum1, 1);
        sum1 += __shfl_xor_sync(0xffffffffu, sum1, 2);
        l0 = l0 * al0 + sum0;
        l1 = l1 * al1 + sum1;
#pragma unroll
        for (int nf = 0; nf < 16; nf++) {
            o[nf][0] *= al0; o[nf][1] *= al0;
            o[nf][2] *= al1; o[nf][3] *= al1;
        }

#pragma unroll
        for (int j = 0; j < 8; j++) {
            uint32_t pa[4];
            pa[0] = h2u(s[2 * j][0],     s[2 * j][1]);
            pa[1] = h2u(s[2 * j][2],     s[2 * j][3]);
            pa[2] = h2u(s[2 * j + 1][0], s[2 * j + 1][1]);
            pa[3] = h2u(s[2 * j + 1][2], s[2 * j + 1][3]);
            int s_off = 16 * j + vs_lane;
#pragma unroll
            for (int nd2 = 0; nd2 < 8; nd2++) {
                int d_chunk = nd2 * 2 + vd_half;
                uint32_t sw = (uint32_t)((d_chunk & ~7) | ((d_chunk & 7) ^ (s_off & 7)));
                uint32_t bf[4];
                ldsm4t(bf, sV + s_off * 256 + sw * 16);
                mma_f16(o[2 * nd2],     pa, bf[0], bf[1]);
                mma_f16(o[2 * nd2 + 1], pa, bf[2], bf[3]);
            }
        }
        __syncthreads();
    }

    float il0 = 1.f / l0, il1 = 1.f / l1;
    int sg = q0 + wrow + lr;
    __half* a0 = attn + ((long long)(b * S_ + sg) * (H_ * D_V)) + h * D_V;
    __half* a1 = a0 + (long long)8 * (H_ * D_V);
#pragma unroll
    for (int nf = 0; nf < 16; nf++) {
        int d = nf * 8 + 2 * lc;
        *(__half2*)(a0 + d) = __floats2half2_rn(o[nf][0] * il0, o[nf][1] * il0);
        *(__half2*)(a1 + d) = __floats2half2_rn(o[nf][2] * il1, o[nf][3] * il1);
    }
}

// ---------------- fp32 -> fp16 convert ----------------
__global__ void cvt_f2h_kernel(const float* __restrict__ in, __half* __restrict__ out, int n4)
{
    int i = blockIdx.x * blockDim.x + threadIdx.x;
    int stride = gridDim.x * blockDim.x;
    for (; i < n4; i += stride) {
        float4 v = ((const float4*)in)[i];
        __half2 h0 = __floats2half2_rn(v.x, v.y);
        __half2 h1 = __floats2half2_rn(v.z, v.w);
        *(uint2*)(out + (size_t)i * 4) = make_uint2(*(uint32_t*)&h0, *(uint32_t*)&h1);
    }
}

// ---------------- fused dual RMSNorm (half in strided, half out) ----------------
__global__ void rmsnorm2_kernel(const __half* __restrict__ proj1,
                                const float* __restrict__ qw, const float* __restrict__ kw,
                                __half* __restrict__ qan, __half* __restrict__ kvc)
{
    long long row = blockIdx.x;
    int which = blockIdx.y;
    int width = which ? KV_LORA : Q_LORA;
    const __half* x = proj1 + row * NPROJ1 + (which ? Q_LORA : 0);
    const float* w = which ? kw : qw;
    __half* o = which ? (kvc + row * KV_LORA) : (qan + row * Q_LORA);
    __shared__ float red[256];
    int t = threadIdx.x;
    float ss = 0.f;
    for (int i = t; i < width; i += 256) { float v = __half2float(x[i]); ss += v * v; }
    red[t] = ss;
    __syncthreads();
    for (int s = 128; s > 0; s >>= 1) {
        if (t < s) red[t] += red[t + s];
        __syncthreads();
    }
    float scale = rsqrtf(red[0] / (float)width + 1e-6f);
    for (int i = t; i < width; i += 256)
        o[i] = __float2half_rn(__half2float(x[i]) * scale * w[i]);
}

// ---------------- RoPE: in-place on qfull pe slices + kpe extraction (R12) ----------------
__global__ void rope_kernel(__half* __restrict__ qfull, const __half* __restrict__ proj1,
                            const float* __restrict__ freqs, __half* __restrict__ kpe)
{
    int bs = blockIdx.x;
    int s  = bs & (S_ - 1);
    const float* fr = freqs + (long long)s * D_ROPE;
    int t = threadIdx.x;
    for (int i = t; i < 544; i += 128) {
        if (i < 512) {
            int h = i >> 5, p = i & 31;
            __half* q = qfull + ((long long)bs * H_ + h) * D_QK + D_NOPE + 2 * p;
            float c  = fr[2 * p], sn = fr[2 * p + 1];
            float x0 = __half2float(q[0]);
            float x1 = __half2float(q[1]);
            q[0] = __float2half_rn(x0 * c - x1 * sn);
            q[1] = __float2half_rn(x0 * sn + x1 * c);
        } else {
            int p = i - 512;
            const __half* kp = proj1 + (long long)bs * NPROJ1 + (Q_LORA + KV_LORA) + 2 * p;
            float c  = fr[2 * p], sn = fr[2 * p + 1];
            float y0 = __half2float(kp[0]);
            float y1 = __half2float(kp[1]);
            __half* ko = kpe + (long long)bs * D_ROPE + 2 * p;
            ko[0] = __float2half_rn(y0 * c - y1 * sn);
            ko[1] = __float2half_rn(y0 * sn + y1 * c);
        }
    }
}

// ---------------- launch helpers ----------------
static void launch_gemm_s(cudaStream_t st, const __half* A, const __half* Bm, void* C,
                          int M, int N, int K, int lda, int ldb, int ldc,
                          float alpha, int flags)
{
    dim3 grid((N + 127) / 128, (M + 127) / 128, 1);
    gemm_h<<<grid, 256, SMEM_BYTES, st>>>(A, Bm, C, M, N, K, lda, ldb, ldc, alpha, flags);
}

static void launch_cvt_s(cudaStream_t st, const float* in, __half* out, size_t n)
{
    int n4 = (int)(n / 4);
    int blocks = (n4 + 255) / 256;
    if (blocks > 8192) blocks = 8192;
    cvt_f2h_kernel<<<blocks, 256, 0, st>>>(in, out, n4);
}

// ---- lazily-initialized streams/events (created ONCE on first call = part of
// the harness's pre-capture baseline; no per-call allocation) ----
struct StreamCtx {
    cudaStream_t s2, s3;
    cudaEvent_t eFork, eWc, eW, eW2, eWo, eN, e4;
    StreamCtx() {
        cudaStreamCreateWithFlags(&s2, cudaStreamNonBlocking);
        cudaStreamCreateWithFlags(&s3, cudaStreamNonBlocking);
        cudaEventCreateWithFlags(&eFork, cudaEventDisableTiming);
        cudaEventCreateWithFlags(&eWc,   cudaEventDisableTiming);
        cudaEventCreateWithFlags(&eW,    cudaEventDisableTiming);
        cudaEventCreateWithFlags(&eW2,   cudaEventDisableTiming);
        cudaEventCreateWithFlags(&eWo,   cudaEventDisableTiming);
        cudaEventCreateWithFlags(&eN,    cudaEventDisableTiming);
        cudaEventCreateWithFlags(&e4,    cudaEventDisableTiming);
    }
};

extern "C" void kernel_launch(void* const* d_in, const int* in_sizes, int n_in,
                              void* d_out, int out_size)
{
    const float* x     = (const float*)d_in[0];
    const float* freqs = (const float*)d_in[1];
    const float* Wqa   = (const float*)d_in[2];
    const float* qlnw  = (const float*)d_in[3];
    const float* Wqb   = (const float*)d_in[4];
    const float* Wkva  = (const float*)d_in[5];
    const float* kvlnw = (const float*)d_in[6];
    const float* Wkvb  = (const float*)d_in[7];
    const float* Wo    = (const float*)d_in[8];
    float* out = (float*)d_out;

    cudaFuncSetAttribute(gemm_h, cudaFuncAttributeMaxDynamicSharedMemorySize, SMEM_BYTES);
    cudaFuncSetAttribute(flash_kernel, cudaFuncAttributeMaxDynamicSharedMemorySize, FSMEM);

    __half *proj1, *xh, *wcomb, *wqbh, *wkvbh, *woh;
    __half *qan, *kvc, *qfull, *kvb, *kpe, *attn;
    cudaGetSymbolAddress((void**)&proj1,  g_proj1);
    cudaGetSymbolAddress((void**)&xh,     g_xh);
    cudaGetSymbolAddress((void**)&wcomb,  g_wcomb);
    cudaGetSymbolAddress((void**)&wqbh,   g_wqbh);
    cudaGetSymbolAddress((void**)&wkvbh,  g_wkvbh);
    cudaGetSymbolAddress((void**)&woh,    g_woh);
    cudaGetSymbolAddress((void**)&qan,    g_qan);
    cudaGetSymbolAddress((void**)&kvc,    g_kvc);
    cudaGetSymbolAddress((void**)&qfull,  g_qfull);
    cudaGetSymbolAddress((void**)&kvb,    g_kvb);
    cudaGetSymbolAddress((void**)&kpe,    g_kpe);
    cudaGetSymbolAddress((void**)&attn,   g_attn);

    const float SCALE = 1.0f / sqrtf((float)D_QK);
    const int HOUT = 4;
    cudaStream_t s0 = 0;

    static StreamCtx ctx;          // created once on first (correctness) call
    cudaStream_t s2 = ctx.s2, s3 = ctx.s3;

    // fork s2/s3 off the capture (NULL) stream
    cudaEventRecord(ctx.eFork, s0);
    cudaStreamWaitEvent(s2, ctx.eFork, 0);
    cudaStreamWaitEvent(s3, ctx.eFork, 0);

    // s3: weight converts for later GEMMs
    launch_cvt_s(s3, Wqb,  wqbh,  (size_t)H_ * D_QK * Q_LORA);
    cudaEventRecord(ctx.eW, s3);
    launch_cvt_s(s3, Wkvb, wkvbh, (size_t)H_ * (D_NOPE + D_V) * KV_LORA);
    cudaEventRecord(ctx.eW2, s3);
    launch_cvt_s(s3, Wo,   woh,   (size_t)D_ * H_ * D_V);
    cudaEventRecord(ctx.eWo, s3);

    // s2: convert Wqa + Wkva into wcomb (concurrent with x convert on s0)
    launch_cvt_s(s2, Wqa,  wcomb, (size_t)Q_LORA * D_);
    launch_cvt_s(s2, Wkva, wcomb + (size_t)Q_LORA * D_, (size_t)(KV_LORA + D_ROPE) * D_);
    cudaEventRecord(ctx.eWc, s2);

    // s0: convert x, then GEMM1 + fused RMSNorms
    launch_cvt_s(s0, x, xh, (size_t)BS * D_);
    cudaStreamWaitEvent(s0, ctx.eWc, 0);
    // 1. proj1 = x @ [Wqa;Wkva]^T          [4096,2112] K=2048 -> half
    launch_gemm_s(s0, xh, wcomb, proj1, BS, NPROJ1, D_, D_, D_, NPROJ1, 1.0f, HOUT);
    // 2. fused RMSNorms -> half
    rmsnorm2_kernel<<<dim3(BS, 2), 256, 0, s0>>>(proj1, qlnw, kvlnw, qan, kvc);
    cudaEventRecord(ctx.eN, s0);

    // s2: GEMM4 (needs kvc from eN + wkvbh from eW2)
    cudaStreamWaitEvent(s2, ctx.eN, 0);
    cudaStreamWaitEvent(s2, ctx.eW2, 0);
    // 4. kv_b = kv_c @ Wkvb^T              [4096,4096] K=512 -> half
    launch_gemm_s(s2, kvc, wkvbh, kvb, BS, H_ * (D_NOPE + D_V), KV_LORA, KV_LORA, KV_LORA,
                  H_ * (D_NOPE + D_V), 1.0f, HOUT);
    cudaEventRecord(ctx.e4, s2);

    // s0: GEMM3 (needs wqbh from eW), concurrent with GEMM4 on s2
    cudaStreamWaitEvent(s0, ctx.eW, 0);
    // 3. q_full = q_a_n @ Wqb^T            [4096,3072] K=1536 -> half
    launch_gemm_s(s0, qan, wqbh, qfull, BS, H_ * D_QK, Q_LORA, Q_LORA, Q_LORA, H_ * D_QK,
                  1.0f, HOUT);
    // 5. RoPE (in-place on qfull; kpe extracted from proj1; overlaps GEMM4 tail)
    rope_kernel<<<BS, 128, 0, s0>>>(qfull, proj1, freqs, kpe);

    // join: flash needs GEMM4 output
    cudaStreamWaitEvent(s0, ctx.e4, 0);
    // 6. fused flash attention -> attn (half)
    flash_kernel<<<dim3(S_ / 128, BH), 256, FSMEM, s0>>>(qfull, kvb, kpe, attn, SCALE);
    // 7. out = attn @ Wo^T                 [4096,2048] K=2048 -> fp32
    cudaStreamWaitEvent(s0, ctx.eWo, 0);
    launch_gemm_s(s0, attn, woh, out, BS, D_, H_ * D_V, H_ * D_V, H_ * D_V, D_, 1.0f, 0);
}